// round 3
// baseline (speedup 1.0000x reference)
#include <cuda_runtime.h>
#include <cuda_bf16.h>

#define NN 100000
#define NE 800000
#define DD 300
#define NG 64
#define SW 100          // floats per feature slice (3 slices of 100)
#define SW4 25          // float4 lanes per slice row

// ---------------- scratch (device globals; no allocation allowed) ----------
__device__ int   g_cnt[NN];
__device__ int   g_rowptr[NN + 1];
__device__ int   g_wpos[NN];
__device__ int   g_col[NE];
__device__ float g_dinv[NN];
__device__ float g_bufA[(size_t)NN * SW];   // 40 MB — L2-resident
__device__ float g_bufB[(size_t)NN * SW];   // 40 MB — L2-resident
__device__ float g_v1[NN];
__device__ float g_v2[NN];
__device__ float g_Msum[NG * DD];
__device__ float g_usum[2 * NG];   // [0..63]=sum v1 per graph, [64..127]=sum v2
__device__ int   g_gcnt[NG];
__device__ float g_W2[DD * DD];
__device__ float g_W3[DD * DD];
__device__ float g_r1[DD];
__device__ float g_r2[DD];

// ---------------- kernels ---------------------------------------------------

__global__ void zero_kernel() {
    int idx = blockIdx.x * blockDim.x + threadIdx.x;
    int stride = gridDim.x * blockDim.x;
    for (int i = idx; i < NN; i += stride) g_cnt[i] = 0;
    for (int i = idx; i < NG * DD; i += stride) g_Msum[i] = 0.f;
    for (int i = idx; i < 2 * NG; i += stride) g_usum[i] = 0.f;
    for (int i = idx; i < NG; i += stride) g_gcnt[i] = 0;
}

__global__ void hist_kernel(const int* __restrict__ ei) {
    int e = blockIdx.x * blockDim.x + threadIdx.x;
    if (e >= NE) return;
    atomicAdd(&g_cnt[ei[NE + e]], 1);   // dst
}

// single-block exclusive scan over g_cnt -> g_rowptr, also dinv
__global__ void scan_kernel() {
    __shared__ int sh[1024];
    int tid = threadIdx.x;
    const int per = (NN + 1023) / 1024;
    int start = tid * per;
    int end = start + per; if (end > NN) end = NN; if (start > NN) start = NN;
    int s = 0;
    for (int i = start; i < end; ++i) s += g_cnt[i];
    sh[tid] = s;
    __syncthreads();
    for (int off = 1; off < 1024; off <<= 1) {
        int v = 0;
        if (tid >= off) v = sh[tid - off];
        __syncthreads();
        sh[tid] += v;
        __syncthreads();
    }
    int run = (tid > 0) ? sh[tid - 1] : 0;
    for (int i = start; i < end; ++i) {
        g_rowptr[i] = run;
        g_wpos[i]   = run;
        g_dinv[i]   = rsqrtf((float)(g_cnt[i] + 1));   // +1 self loop
        run += g_cnt[i];
    }
    if (tid == 1023) g_rowptr[NN] = sh[1023];
}

__global__ void scatter_kernel(const int* __restrict__ ei) {
    int e = blockIdx.x * blockDim.x + threadIdx.x;
    if (e >= NE) return;
    int dst = ei[NE + e];
    int pos = atomicAdd(&g_wpos[dst], 1);
    g_col[pos] = ei[e];                 // src
}

// hop 1 with embedding fused: h0[s] = at[x[s,0]] + wt[x[s,1]] computed on the fly.
// Writes bufA[i] = dinv[i] * y1[i]  (pre-scaled z1 for the next hop).
// warp per node; lane < 25 handles one float4 of the 100-float slice.
__global__ void agg_first_kernel(const int* __restrict__ x,
                                 const float* __restrict__ at,
                                 const float* __restrict__ wt,
                                 int off) {
    int gt = blockIdx.x * blockDim.x + threadIdx.x;
    int i = gt >> 5;
    int lane = gt & 31;
    if (i >= NN) return;
    bool act = lane < SW4;
    int beg = g_rowptr[i], end = g_rowptr[i + 1];
    float4 acc = make_float4(0.f, 0.f, 0.f, 0.f);
    for (int e = beg; e < end; ++e) {
        int s = g_col[e];
        float w = g_dinv[s];
        int a  = x[2 * s];
        int wd = x[2 * s + 1];
        if (act) {
            float4 va = ((const float4*)(at + (size_t)a  * DD + off))[lane];
            float4 vw = ((const float4*)(wt + (size_t)wd * DD + off))[lane];
            acc.x += w * (va.x + vw.x);
            acc.y += w * (va.y + vw.y);
            acc.z += w * (va.z + vw.z);
            acc.w += w * (va.w + vw.w);
        }
    }
    float di = g_dinv[i];
    if (act) {
        int a  = x[2 * i];
        int wd = x[2 * i + 1];
        float4 va = ((const float4*)(at + (size_t)a  * DD + off))[lane];
        float4 vw = ((const float4*)(wt + (size_t)wd * DD + off))[lane];
        float f = di * di;
        float4 o;
        o.x = f * (acc.x + di * (va.x + vw.x));
        o.y = f * (acc.y + di * (va.y + vw.y));
        o.z = f * (acc.z + di * (va.z + vw.z));
        o.w = f * (acc.w + di * (va.w + vw.w));
        ((float4*)(g_bufA + (size_t)i * SW))[lane] = o;
    }
}

// hops 2/3: input rows are pre-scaled (z = dinv .* y), so gather is a plain sum.
// last=0: out = dinv^2 * (sum + self)   (writes z for next hop)
// last=1: out = dinv   * (sum + self)   (writes the true y3 for pooling)
__global__ void agg_step_kernel(const float* __restrict__ in,
                                float* __restrict__ out, int last) {
    int gt = blockIdx.x * blockDim.x + threadIdx.x;
    int i = gt >> 5;
    int lane = gt & 31;
    if (i >= NN) return;
    bool act = lane < SW4;
    int beg = g_rowptr[i], end = g_rowptr[i + 1];
    float4 acc0 = make_float4(0.f, 0.f, 0.f, 0.f);
    float4 acc1 = make_float4(0.f, 0.f, 0.f, 0.f);
    int e = beg;
    for (; e + 1 < end; e += 2) {
        int s0 = g_col[e];
        int s1 = g_col[e + 1];
        if (act) {
            float4 v0 = ((const float4*)(in + (size_t)s0 * SW))[lane];
            float4 v1 = ((const float4*)(in + (size_t)s1 * SW))[lane];
            acc0.x += v0.x; acc0.y += v0.y; acc0.z += v0.z; acc0.w += v0.w;
            acc1.x += v1.x; acc1.y += v1.y; acc1.z += v1.z; acc1.w += v1.w;
        }
    }
    if (e < end && act) {
        int s0 = g_col[e];
        float4 v0 = ((const float4*)(in + (size_t)s0 * SW))[lane];
        acc0.x += v0.x; acc0.y += v0.y; acc0.z += v0.z; acc0.w += v0.w;
    }
    float di = g_dinv[i];
    if (act) {
        float4 self = ((const float4*)(in + (size_t)i * SW))[lane];
        float f = last ? di : di * di;
        float4 o;
        o.x = f * (acc0.x + acc1.x + self.x);
        o.y = f * (acc0.y + acc1.y + self.y);
        o.z = f * (acc0.z + acc1.z + self.z);
        o.w = f * (acc0.w + acc1.w + self.w);
        ((float4*)(out + (size_t)i * SW))[lane] = o;
    }
}

// scalar aggregation; ones=1 means input vector is all-ones
__global__ void aggs_kernel(const float* __restrict__ vin, float* __restrict__ vout, int ones) {
    int i = blockIdx.x * blockDim.x + threadIdx.x;
    if (i >= NN) return;
    int beg = g_rowptr[i];
    int end = g_rowptr[i + 1];
    float sum = 0.f;
    for (int e = beg; e < end; ++e) {
        int s = g_col[e];
        float w = g_dinv[s];
        sum += ones ? w : w * vin[s];
    }
    float di = g_dinv[i];
    float self = ones ? 1.f : vin[i];
    vout[i] = di * (sum + di * self);
}

// mean-pool partial sums for one feature slice (batch sorted): run-length + flush
__global__ void pool_kernel(const float* __restrict__ h, const int* __restrict__ batch,
                            int off) {
    const int CH = 512;
    int n0 = blockIdx.x * CH;
    int n1 = n0 + CH; if (n1 > NN) n1 = NN;
    int t = threadIdx.x;                // 0..127, only t<SW carries data
    float acc = 0.f;
    int cur = batch[n0];
    for (int n = n0; n < n1; ++n) {
        int g = batch[n];
        if (g != cur) {
            if (t < SW) atomicAdd(&g_Msum[cur * DD + off + t], acc);
            acc = 0.f;
            cur = g;
        }
        if (t < SW) acc += h[(size_t)n * SW + t];
    }
    if (t < SW) atomicAdd(&g_Msum[cur * DD + off + t], acc);
}

__global__ void vpool_kernel(const int* __restrict__ batch) {
    int i = blockIdx.x * blockDim.x + threadIdx.x;
    if (i >= NN) return;
    int bg = batch[i];
    atomicAdd(&g_gcnt[bg], 1);
    atomicAdd(&g_usum[bg], g_v1[i]);
    atomicAdd(&g_usum[NG + bg], g_v2[i]);
}

// C = A @ B, all 300x300 row-major
__global__ void gemm300_kernel(const float* __restrict__ A,
                               const float* __restrict__ B,
                               float* __restrict__ C) {
    int r = blockIdx.x;
    int c = threadIdx.x;
    if (c >= DD) return;
    float acc = 0.f;
    for (int k = 0; k < DD; ++k) acc += A[r * DD + k] * B[k * DD + c];
    C[r * DD + c] = acc;
}

// r1 = b^T W, r2 = b^T W2
__global__ void rvec_kernel(const float* __restrict__ b,
                            const float* __restrict__ W) {
    int c = blockIdx.x * blockDim.x + threadIdx.x;
    if (c >= DD) return;
    float a1 = 0.f, a2 = 0.f;
    for (int k = 0; k < DD; ++k) {
        float bk = b[k];
        a1 += bk * W[k * DD + c];
        a2 += bk * g_W2[k * DD + c];
    }
    g_r1[c] = a1;
    g_r2[c] = a2;
}

// out[g] = (Msum[g]@W3 + u2sum*r2 + u1sum*r1)/max(cnt,1) + (cnt>0)*b
__global__ void final_kernel(const float* __restrict__ bvec, float* __restrict__ out) {
    int g = blockIdx.x;
    int d = threadIdx.x;
    if (d >= DD) return;
    float acc = 0.f;
    for (int k = 0; k < DD; ++k) acc += g_Msum[g * DD + k] * g_W3[k * DD + d];
    int c = g_gcnt[g];
    float denom = (c > 0) ? (float)c : 1.f;
    float res = (acc + g_usum[NG + g] * g_r2[d] + g_usum[g] * g_r1[d]) / denom;
    if (c > 0) res += bvec[d];
    out[g * DD + d] = res;
}

// ---------------- launch ----------------------------------------------------

extern "C" void kernel_launch(void* const* d_in, const int* in_sizes, int n_in,
                              void* d_out, int out_size) {
    const int*   x     = (const int*)d_in[0];     // [N,2]
    const int*   ei    = (const int*)d_in[1];     // [2,E]
    const int*   batch = (const int*)d_in[2];     // [N]
    const float* at    = (const float*)d_in[3];   // [41,300]
    const float* wt    = (const float*)d_in[4];   // [10000,300]
    const float* W     = (const float*)d_in[5];   // [300,300]
    const float* b     = (const float*)d_in[6];   // [300]
    float* out = (float*)d_out;

    float *bufA, *bufB, *v1, *v2, *W2p, *W3p;
    cudaGetSymbolAddress((void**)&bufA, g_bufA);
    cudaGetSymbolAddress((void**)&bufB, g_bufB);
    cudaGetSymbolAddress((void**)&v1,   g_v1);
    cudaGetSymbolAddress((void**)&v2,   g_v2);
    cudaGetSymbolAddress((void**)&W2p,  g_W2);
    cudaGetSymbolAddress((void**)&W3p,  g_W3);

    const int AGG_GRID = (NN * 32 + 255) / 256;   // warp per node

    // 1) zero accumulators
    zero_kernel<<<512, 256>>>();
    // 2) CSR build (by dst)
    hist_kernel<<<(NE + 255) / 256, 256>>>(ei);
    scan_kernel<<<1, 1024>>>();
    scatter_kernel<<<(NE + 255) / 256, 256>>>(ei);
    // 3) scalar aggregations for the bias terms: v1 = A*1, v2 = A*v1
    aggs_kernel<<<(NN + 255) / 256, 256>>>(nullptr, v1, 1);
    aggs_kernel<<<(NN + 255) / 256, 256>>>(v1, v2, 0);
    vpool_kernel<<<(NN + 255) / 256, 256>>>(batch);
    // 4) feature-sliced 3-hop aggregation chain (buffers stay L2-resident)
    for (int s = 0; s < 3; ++s) {
        int off = s * SW;
        agg_first_kernel<<<AGG_GRID, 256>>>(x, at, wt, off);          // -> bufA (z1)
        agg_step_kernel <<<AGG_GRID, 256>>>(bufA, bufB, 0);           // -> bufB (z2)
        agg_step_kernel <<<AGG_GRID, 256>>>(bufB, bufA, 1);           // -> bufA (y3)
        pool_kernel<<<(NN + 511) / 512, 128>>>(bufA, batch, off);     // Msum slice
    }
    // 5) tiny GEMMs: W2 = W@W, W3 = W2@W, r-vectors
    gemm300_kernel<<<DD, 320>>>(W, W, W2p);
    gemm300_kernel<<<DD, 320>>>(W2p, W, W3p);
    rvec_kernel<<<1, 320>>>(b, W);
    // 6) finisher: 64x300 output
    final_kernel<<<NG, 320>>>(b, out);
}

// round 4
// speedup vs baseline: 1.2886x; 1.2886x over previous
#include <cuda_runtime.h>
#include <cuda_fp16.h>

#define NN 100000
#define NE 800000
#define DD 300
#define DH 150          // half2 lanes per row
#define NG 64

// ---------------- scratch (device globals; no allocation allowed) ----------
__device__ int     g_cnt[NN];          // zeroed by scan after use (self-resetting)
__device__ int     g_rowptr[NN + 1];
__device__ int     g_wpos[NN];
__device__ int     g_col[NE];
__device__ float   g_dinv[NN];
__device__ __half2 g_hA[(size_t)NN * DH];   // 60 MB
__device__ __half2 g_hB[(size_t)NN * DH];   // 60 MB
__device__ float   g_v1[NN];
__device__ float   g_v2[NN];
__device__ float   g_Msum[NG * DD];
__device__ float   g_usum[2 * NG];
__device__ int     g_gcnt[NG];
__device__ float   g_W2[DD * DD];
__device__ float   g_W3[DD * DD];
__device__ float   g_r1[DD];
__device__ float   g_r2[DD];

// ---------------- kernels ---------------------------------------------------

// g_cnt starts at 0 (bss on first call; zeroed by scan_kernel on every call)
__global__ void hist_kernel(const int* __restrict__ ei) {
    int e = blockIdx.x * blockDim.x + threadIdx.x;
    if (e >= NE) return;
    atomicAdd(&g_cnt[ei[NE + e]], 1);   // dst
}

// single-block exclusive scan over g_cnt -> g_rowptr/g_wpos, dinv; then
// resets g_cnt to 0 and zeroes the pooling accumulators for this call.
__global__ void scan_kernel() {
    __shared__ int sh[1024];
    int tid = threadIdx.x;
    const int per = (NN + 1023) / 1024;
    int start = tid * per;
    int end = start + per; if (end > NN) end = NN; if (start > NN) start = NN;
    int s = 0;
    for (int i = start; i < end; ++i) s += g_cnt[i];
    sh[tid] = s;
    __syncthreads();
    for (int off = 1; off < 1024; off <<= 1) {
        int v = 0;
        if (tid >= off) v = sh[tid - off];
        __syncthreads();
        sh[tid] += v;
        __syncthreads();
    }
    int run = (tid > 0) ? sh[tid - 1] : 0;
    for (int i = start; i < end; ++i) {
        int c = g_cnt[i];
        g_rowptr[i] = run;
        g_wpos[i]   = run;
        g_dinv[i]   = rsqrtf((float)(c + 1));   // +1 self loop
        run += c;
        g_cnt[i] = 0;                            // reset for next call
    }
    if (tid == 1023) g_rowptr[NN] = sh[1023];
    // zero accumulators (consumed later this call)
    for (int i = tid; i < NG * DD; i += 1024) g_Msum[i] = 0.f;
    if (tid < 2 * NG) g_usum[tid] = 0.f;
    if (tid < NG)     g_gcnt[tid] = 0;
}

// fused: CSR column scatter (per edge) + embedding z0 = dinv*(at[a]+wt[w]) (per element)
#define EDGE_BLOCKS ((NE + 255) / 256)
#define EMB_ITEMS   (NN * DH)
#define EMB_BLOCKS  ((EMB_ITEMS + 255) / 256)
__global__ void scatter_embed_kernel(const int* __restrict__ ei,
                                     const int* __restrict__ x,
                                     const float* __restrict__ at,
                                     const float* __restrict__ wt) {
    if (blockIdx.x < EDGE_BLOCKS) {
        int e = blockIdx.x * 256 + threadIdx.x;
        if (e >= NE) return;
        int dst = ei[NE + e];
        int pos = atomicAdd(&g_wpos[dst], 1);
        g_col[pos] = ei[e];                 // src
    } else {
        int idx = (blockIdx.x - EDGE_BLOCKS) * 256 + threadIdx.x;
        if (idx >= EMB_ITEMS) return;
        int i = idx / DH;
        int t = idx - i * DH;               // half2 lane (float2 of the tables)
        int a  = x[2 * i];
        int w  = x[2 * i + 1];
        float2 va = ((const float2*)at)[a * DH + t];
        float2 vw = ((const float2*)wt)[w * DH + t];
        float di = g_dinv[i];
        float2 z = make_float2(di * (va.x + vw.x), di * (va.y + vw.y));
        g_hA[(size_t)i * DH + t] = __float22half2_rn(z);
    }
}

// one GCN hop on pre-scaled rows. in rows are z = dinv .* y.
// last=0: out = dinv^2 * (sum + self)   (z for next hop)
// last=1: out = dinv   * (sum + self)   (true y3 for pooling)
__global__ void agg_step_kernel(const __half2* __restrict__ in,
                                __half2* __restrict__ out, int last) {
    int i = blockIdx.x;
    int t = threadIdx.x;                // 0..159, active t<150
    bool act = t < DH;
    int beg = g_rowptr[i], end = g_rowptr[i + 1];
    float2 a0 = make_float2(0.f, 0.f);
    float2 a1 = make_float2(0.f, 0.f);
    int e = beg;
    for (; e + 1 < end; e += 2) {
        int s0 = g_col[e];
        int s1 = g_col[e + 1];
        if (act) {
            float2 v0 = __half22float2(in[(size_t)s0 * DH + t]);
            float2 v1 = __half22float2(in[(size_t)s1 * DH + t]);
            a0.x += v0.x; a0.y += v0.y;
            a1.x += v1.x; a1.y += v1.y;
        }
    }
    if (e < end && act) {
        int s0 = g_col[e];
        float2 v0 = __half22float2(in[(size_t)s0 * DH + t]);
        a0.x += v0.x; a0.y += v0.y;
    }
    float di = g_dinv[i];
    if (act) {
        float2 self = __half22float2(in[(size_t)i * DH + t]);
        float f = last ? di : di * di;
        float2 r = make_float2(f * (a0.x + a1.x + self.x),
                               f * (a0.y + a1.y + self.y));
        out[(size_t)i * DH + t] = __float22half2_rn(r);
    }
}

// scalar aggregation for the bias terms; ones=1 -> input is all-ones
__global__ void aggs_kernel(const float* __restrict__ vin, float* __restrict__ vout, int ones) {
    int i = blockIdx.x * blockDim.x + threadIdx.x;
    if (i >= NN) return;
    int beg = g_rowptr[i];
    int end = g_rowptr[i + 1];
    float sum = 0.f;
    for (int e = beg; e < end; ++e) {
        int s = g_col[e];
        float w = g_dinv[s];
        sum += ones ? w : w * vin[s];
    }
    float di = g_dinv[i];
    float self = ones ? 1.f : vin[i];
    vout[i] = di * (sum + di * self);
}

// mean-pool partial sums (batch sorted): run-length accumulate, atomic flush
__global__ void pool_kernel(const __half2* __restrict__ h, const int* __restrict__ batch) {
    const int CH = 512;
    int n0 = blockIdx.x * CH;
    int n1 = n0 + CH; if (n1 > NN) n1 = NN;
    int t = threadIdx.x;                // 0..159, active t<150
    bool act = t < DH;
    float2 acc = make_float2(0.f, 0.f);
    int cur = batch[n0];
    for (int n = n0; n < n1; ++n) {
        int g = batch[n];
        if (g != cur) {
            if (act) {
                atomicAdd(&g_Msum[cur * DD + 2 * t],     acc.x);
                atomicAdd(&g_Msum[cur * DD + 2 * t + 1], acc.y);
            }
            acc = make_float2(0.f, 0.f);
            cur = g;
        }
        if (act) {
            float2 v = __half22float2(h[(size_t)n * DH + t]);
            acc.x += v.x; acc.y += v.y;
        }
    }
    if (act) {
        atomicAdd(&g_Msum[cur * DD + 2 * t],     acc.x);
        atomicAdd(&g_Msum[cur * DD + 2 * t + 1], acc.y);
    }
}

__global__ void vpool_kernel(const int* __restrict__ batch) {
    int i = blockIdx.x * blockDim.x + threadIdx.x;
    if (i >= NN) return;
    int bg = batch[i];
    atomicAdd(&g_gcnt[bg], 1);
    atomicAdd(&g_usum[bg], g_v1[i]);
    atomicAdd(&g_usum[NG + bg], g_v2[i]);
}

// C = A @ B, all 300x300 row-major
__global__ void gemm300_kernel(const float* __restrict__ A,
                               const float* __restrict__ B,
                               float* __restrict__ C) {
    int r = blockIdx.x;
    int c = threadIdx.x;
    if (c >= DD) return;
    float acc = 0.f;
    for (int k = 0; k < DD; ++k) acc += A[r * DD + k] * B[k * DD + c];
    C[r * DD + c] = acc;
}

// r1 = b^T W, r2 = b^T W2
__global__ void rvec_kernel(const float* __restrict__ b,
                            const float* __restrict__ W) {
    int c = blockIdx.x * blockDim.x + threadIdx.x;
    if (c >= DD) return;
    float a1 = 0.f, a2 = 0.f;
    for (int k = 0; k < DD; ++k) {
        float bk = b[k];
        a1 += bk * W[k * DD + c];
        a2 += bk * g_W2[k * DD + c];
    }
    g_r1[c] = a1;
    g_r2[c] = a2;
}

// out[g] = (Msum[g]@W3 + u2sum*r2 + u1sum*r1)/max(cnt,1) + (cnt>0)*b
__global__ void final_kernel(const float* __restrict__ bvec, float* __restrict__ out) {
    int g = blockIdx.x;
    int d = threadIdx.x;
    if (d >= DD) return;
    float acc = 0.f;
    for (int k = 0; k < DD; ++k) acc += g_Msum[g * DD + k] * g_W3[k * DD + d];
    int c = g_gcnt[g];
    float denom = (c > 0) ? (float)c : 1.f;
    float res = (acc + g_usum[NG + g] * g_r2[d] + g_usum[g] * g_r1[d]) / denom;
    if (c > 0) res += bvec[d];
    out[g * DD + d] = res;
}

// ---------------- launch ----------------------------------------------------

extern "C" void kernel_launch(void* const* d_in, const int* in_sizes, int n_in,
                              void* d_out, int out_size) {
    const int*   x     = (const int*)d_in[0];     // [N,2]
    const int*   ei    = (const int*)d_in[1];     // [2,E]
    const int*   batch = (const int*)d_in[2];     // [N]
    const float* at    = (const float*)d_in[3];   // [41,300]
    const float* wt    = (const float*)d_in[4];   // [10000,300]
    const float* W     = (const float*)d_in[5];   // [300,300]
    const float* b     = (const float*)d_in[6];   // [300]
    float* out = (float*)d_out;

    __half2 *hA, *hB;
    float *v1, *v2, *W2p, *W3p;
    cudaGetSymbolAddress((void**)&hA,  g_hA);
    cudaGetSymbolAddress((void**)&hB,  g_hB);
    cudaGetSymbolAddress((void**)&v1,  g_v1);
    cudaGetSymbolAddress((void**)&v2,  g_v2);
    cudaGetSymbolAddress((void**)&W2p, g_W2);
    cudaGetSymbolAddress((void**)&W3p, g_W3);

    // 0-2: CSR build + embedding (g_cnt is self-resetting via scan_kernel)
    hist_kernel<<<(NE + 255) / 256, 256>>>(ei);                          // 0
    scan_kernel<<<1, 1024>>>();                                          // 1
    scatter_embed_kernel<<<EDGE_BLOCKS + EMB_BLOCKS, 256>>>(ei, x, at, wt); // 2
    // 3-5: three hops (launch index 3 = ncu capture slot)
    agg_step_kernel<<<NN, 160>>>(hA, hB, 0);                             // 3
    agg_step_kernel<<<NN, 160>>>(hB, hA, 0);                             // 4
    agg_step_kernel<<<NN, 160>>>(hA, hB, 1);                             // 5 -> y3 in hB
    // 6: pooling of y3
    pool_kernel<<<(NN + 511) / 512, 160>>>(hB, batch);                   // 6
    // 7-9: bias-term scalar chain + its pooling
    aggs_kernel<<<(NN + 255) / 256, 256>>>(nullptr, v1, 1);              // 7
    aggs_kernel<<<(NN + 255) / 256, 256>>>(v1, v2, 0);                   // 8
    vpool_kernel<<<(NN + 255) / 256, 256>>>(batch);                      // 9
    // 10-12: tiny GEMMs and r-vectors
    gemm300_kernel<<<DD, 320>>>(W, W, W2p);                              // 10
    gemm300_kernel<<<DD, 320>>>(W2p, W, W3p);                            // 11
    rvec_kernel<<<1, 320>>>(b, W);                                       // 12
    // 13: finisher
    final_kernel<<<NG, 320>>>(b, out);                                   // 13
}

// round 5
// speedup vs baseline: 2.1194x; 1.6446x over previous
#include <cuda_runtime.h>
#include <cuda_fp16.h>

#define NN 100000
#define NE 800000
#define DD 300
#define DH 150          // half2 lanes per row
#define ROWB (DH * 4)   // 600 bytes per row
#define NG 64
#define NB 98           // scan blocks (98 * 1024 >= NN)

// ---------------- scratch (device globals; no allocation allowed) ----------
__device__ int     g_cnt[NN];          // zeroed by scan3 after use (self-resetting)
__device__ int     g_rowptr[NN + 1];
__device__ int     g_wpos[NN];
__device__ int     g_col[NE];          // BYTE offsets (src*600)
__device__ int     g_colidx[NE];       // plain src index (scalar chain)
__device__ float   g_dinv[NN];
__device__ int     g_bsum[NB];
__device__ int     g_boff[NB];
__device__ __half2 g_hA[(size_t)NN * DH];   // 60 MB
__device__ __half2 g_hB[(size_t)NN * DH];   // 60 MB
__device__ float   g_v1[NN];
__device__ float   g_v2[NN];
__device__ float   g_Msum[NG * DD];
__device__ float   g_usum[2 * NG];
__device__ int     g_gcnt[NG];
__device__ float   g_W2[DD * DD];
__device__ float   g_W3[DD * DD];
__device__ float   g_r1[DD];
__device__ float   g_r2[DD];

// ---------------- CSR build --------------------------------------------------

__global__ void hist_kernel(const int* __restrict__ ei) {
    int e = blockIdx.x * blockDim.x + threadIdx.x;
    if (e >= NE) return;
    atomicAdd(&g_cnt[ei[NE + e]], 1);   // dst
}

// phase 1: per-block sum of cnt (coalesced) + dinv
__global__ void scan1_kernel() {
    __shared__ int sh[1024];
    int i = blockIdx.x * 1024 + threadIdx.x;
    int c = 0;
    if (i < NN) {
        c = g_cnt[i];
        g_dinv[i] = rsqrtf((float)(c + 1));   // +1 self loop
    }
    sh[threadIdx.x] = c;
    __syncthreads();
    for (int off = 512; off > 0; off >>= 1) {
        if (threadIdx.x < off) sh[threadIdx.x] += sh[threadIdx.x + off];
        __syncthreads();
    }
    if (threadIdx.x == 0) g_bsum[blockIdx.x] = sh[0];
}

// phase 2: tiny exclusive scan of NB block sums; zero accumulators
__global__ void scan2_kernel() {
    __shared__ int sh[NB];
    int tid = threadIdx.x;
    if (tid < NB) sh[tid] = g_bsum[tid];
    __syncthreads();
    if (tid == 0) {
        int run = 0;
        for (int b = 0; b < NB; ++b) { g_boff[b] = run; run += sh[b]; }
        g_rowptr[NN] = run;   // == NE
    }
    for (int i = tid; i < NG * DD; i += blockDim.x) g_Msum[i] = 0.f;
    if (tid < 2 * NG) g_usum[tid] = 0.f;
    if (tid < NG)     g_gcnt[tid] = 0;
}

// phase 3: per-block exclusive scan, coalesced writes; reset cnt
__global__ void scan3_kernel() {
    __shared__ int sh[1024];
    int tid = threadIdx.x;
    int i = blockIdx.x * 1024 + tid;
    int c = (i < NN) ? g_cnt[i] : 0;
    sh[tid] = c;
    __syncthreads();
    // Hillis-Steele inclusive scan
    for (int off = 1; off < 1024; off <<= 1) {
        int v = (tid >= off) ? sh[tid - off] : 0;
        __syncthreads();
        sh[tid] += v;
        __syncthreads();
    }
    if (i < NN) {
        int excl = g_boff[blockIdx.x] + sh[tid] - c;
        g_rowptr[i] = excl;
        g_wpos[i]   = excl;
        g_cnt[i]    = 0;        // self-reset for next call
    }
}

// fused: CSR column scatter (per edge) + embedding z0 = dinv*(at[a]+wt[w])
#define EDGE_BLOCKS ((NE + 255) / 256)
#define EMB_ITEMS   (NN * DH)
#define EMB_BLOCKS  ((EMB_ITEMS + 255) / 256)
__global__ void scatter_embed_kernel(const int* __restrict__ ei,
                                     const int* __restrict__ x,
                                     const float* __restrict__ at,
                                     const float* __restrict__ wt) {
    if (blockIdx.x < EDGE_BLOCKS) {
        int e = blockIdx.x * 256 + threadIdx.x;
        if (e >= NE) return;
        int dst = ei[NE + e];
        int src = ei[e];
        int pos = atomicAdd(&g_wpos[dst], 1);
        g_col[pos]    = src * ROWB;     // byte offset
        g_colidx[pos] = src;
    } else {
        int idx = (blockIdx.x - EDGE_BLOCKS) * 256 + threadIdx.x;
        if (idx >= EMB_ITEMS) return;
        int i = idx / DH;
        int t = idx - i * DH;
        int a  = x[2 * i];
        int w  = x[2 * i + 1];
        float2 va = ((const float2*)at)[a * DH + t];
        float2 vw = ((const float2*)wt)[w * DH + t];
        float di = g_dinv[i];
        float2 z = make_float2(di * (va.x + vw.x), di * (va.y + vw.y));
        g_hA[(size_t)i * DH + t] = __float22half2_rn(z);
    }
}

// one GCN hop on pre-scaled rows (z = dinv .* y), half2 accumulation.
// last=0: out = dinv^2 * (sum + self)   (z for next hop)
// last=1: out = dinv   * (sum + self)   (true y3 for pooling)
__global__ void agg_step_kernel(const __half2* __restrict__ in,
                                __half2* __restrict__ out, int last) {
    int i = blockIdx.x;
    int t = threadIdx.x;                // 0..159, active t<150
    bool act = t < DH;
    int beg = g_rowptr[i], end = g_rowptr[i + 1];
    const char* base = (const char*)in + t * 4;
    __half2 z2 = __float2half2_rn(0.f);
    __half2 a0 = z2, a1 = z2, a2 = z2, a3 = z2;
    int e = beg;
    for (; e + 4 <= end; e += 4) {
        int o0 = g_col[e];
        int o1 = g_col[e + 1];
        int o2 = g_col[e + 2];
        int o3 = g_col[e + 3];
        if (act) {
            a0 = __hadd2(a0, *(const __half2*)(base + o0));
            a1 = __hadd2(a1, *(const __half2*)(base + o1));
            a2 = __hadd2(a2, *(const __half2*)(base + o2));
            a3 = __hadd2(a3, *(const __half2*)(base + o3));
        }
    }
    for (; e < end; ++e) {
        int o0 = g_col[e];
        if (act) a0 = __hadd2(a0, *(const __half2*)(base + o0));
    }
    if (act) {
        float2 f0 = __half22float2(a0);
        float2 f1 = __half22float2(a1);
        float2 f2 = __half22float2(a2);
        float2 f3 = __half22float2(a3);
        float2 self = __half22float2(*(const __half2*)(base + i * ROWB));
        float di = g_dinv[i];
        float f = last ? di : di * di;
        float2 r = make_float2(f * ((f0.x + f1.x) + (f2.x + f3.x) + self.x),
                               f * ((f0.y + f1.y) + (f2.y + f3.y) + self.y));
        *(__half2*)((char*)out + i * ROWB + t * 4) = __float22half2_rn(r);
    }
}

// scalar aggregation for the bias terms; ones=1 -> input is all-ones
__global__ void aggs_kernel(const float* __restrict__ vin, float* __restrict__ vout, int ones) {
    int i = blockIdx.x * blockDim.x + threadIdx.x;
    if (i >= NN) return;
    int beg = g_rowptr[i];
    int end = g_rowptr[i + 1];
    float sum = 0.f;
    for (int e = beg; e < end; ++e) {
        int s = g_colidx[e];
        float w = g_dinv[s];
        sum += ones ? w : w * vin[s];
    }
    float di = g_dinv[i];
    float self = ones ? 1.f : vin[i];
    vout[i] = di * (sum + di * self);
}

// mean-pool partial sums (batch sorted): run-length accumulate, atomic flush
__global__ void pool_kernel(const __half2* __restrict__ h, const int* __restrict__ batch) {
    const int CH = 128;
    int n0 = blockIdx.x * CH;
    int n1 = n0 + CH; if (n1 > NN) n1 = NN;
    int t = threadIdx.x;                // 0..159, active t<150
    bool act = t < DH;
    float2 acc = make_float2(0.f, 0.f);
    int cur = batch[n0];
    for (int n = n0; n < n1; ++n) {
        int g = batch[n];
        if (g != cur) {
            if (act) {
                atomicAdd(&g_Msum[cur * DD + 2 * t],     acc.x);
                atomicAdd(&g_Msum[cur * DD + 2 * t + 1], acc.y);
            }
            acc = make_float2(0.f, 0.f);
            cur = g;
        }
        if (act) {
            float2 v = __half22float2(h[(size_t)n * DH + t]);
            acc.x += v.x; acc.y += v.y;
        }
    }
    if (act) {
        atomicAdd(&g_Msum[cur * DD + 2 * t],     acc.x);
        atomicAdd(&g_Msum[cur * DD + 2 * t + 1], acc.y);
    }
}

__global__ void vpool_kernel(const int* __restrict__ batch) {
    int i = blockIdx.x * blockDim.x + threadIdx.x;
    if (i >= NN) return;
    int bg = batch[i];
    atomicAdd(&g_gcnt[bg], 1);
    atomicAdd(&g_usum[bg], g_v1[i]);
    atomicAdd(&g_usum[NG + bg], g_v2[i]);
}

// C = A @ B, all 300x300 row-major
__global__ void gemm300_kernel(const float* __restrict__ A,
                               const float* __restrict__ B,
                               float* __restrict__ C) {
    int r = blockIdx.x;
    int c = threadIdx.x;
    if (c >= DD) return;
    float acc = 0.f;
    for (int k = 0; k < DD; ++k) acc += A[r * DD + k] * B[k * DD + c];
    C[r * DD + c] = acc;
}

// r1 = b^T W, r2 = b^T W2
__global__ void rvec_kernel(const float* __restrict__ b,
                            const float* __restrict__ W) {
    int c = blockIdx.x * blockDim.x + threadIdx.x;
    if (c >= DD) return;
    float a1 = 0.f, a2 = 0.f;
    for (int k = 0; k < DD; ++k) {
        float bk = b[k];
        a1 += bk * W[k * DD + c];
        a2 += bk * g_W2[k * DD + c];
    }
    g_r1[c] = a1;
    g_r2[c] = a2;
}

// out[g] = (Msum[g]@W3 + u2sum*r2 + u1sum*r1)/max(cnt,1) + (cnt>0)*b
__global__ void final_kernel(const float* __restrict__ bvec, float* __restrict__ out) {
    int g = blockIdx.x;
    int d = threadIdx.x;
    if (d >= DD) return;
    float acc = 0.f;
    for (int k = 0; k < DD; ++k) acc += g_Msum[g * DD + k] * g_W3[k * DD + d];
    int c = g_gcnt[g];
    float denom = (c > 0) ? (float)c : 1.f;
    float res = (acc + g_usum[NG + g] * g_r2[d] + g_usum[g] * g_r1[d]) / denom;
    if (c > 0) res += bvec[d];
    out[g * DD + d] = res;
}

// ---------------- launch ----------------------------------------------------

extern "C" void kernel_launch(void* const* d_in, const int* in_sizes, int n_in,
                              void* d_out, int out_size) {
    const int*   x     = (const int*)d_in[0];     // [N,2]
    const int*   ei    = (const int*)d_in[1];     // [2,E]
    const int*   batch = (const int*)d_in[2];     // [N]
    const float* at    = (const float*)d_in[3];   // [41,300]
    const float* wt    = (const float*)d_in[4];   // [10000,300]
    const float* W     = (const float*)d_in[5];   // [300,300]
    const float* b     = (const float*)d_in[6];   // [300]
    float* out = (float*)d_out;

    __half2 *hA, *hB;
    float *v1, *v2, *W2p, *W3p;
    cudaGetSymbolAddress((void**)&hA,  g_hA);
    cudaGetSymbolAddress((void**)&hB,  g_hB);
    cudaGetSymbolAddress((void**)&v1,  g_v1);
    cudaGetSymbolAddress((void**)&v2,  g_v2);
    cudaGetSymbolAddress((void**)&W2p, g_W2);
    cudaGetSymbolAddress((void**)&W3p, g_W3);

    // CSR build (coalesced 3-phase scan; g_cnt self-resetting)
    hist_kernel<<<(NE + 255) / 256, 256>>>(ei);                             // 0
    scan1_kernel<<<NB, 1024>>>();                                           // 1
    scan2_kernel<<<1, 256>>>();                                             // 2
    scan3_kernel<<<NB, 1024>>>();                                           // 3
    scatter_embed_kernel<<<EDGE_BLOCKS + EMB_BLOCKS, 256>>>(ei, x, at, wt); // 4
    // three hops (launch 5 = ncu capture slot -> first hop)
    agg_step_kernel<<<NN, 160>>>(hA, hB, 0);                                // 5
    agg_step_kernel<<<NN, 160>>>(hB, hA, 0);                                // 6
    agg_step_kernel<<<NN, 160>>>(hA, hB, 1);                                // 7 -> y3 in hB
    // pooling of y3
    pool_kernel<<<(NN + 127) / 128, 160>>>(hB, batch);                      // 8
    // bias-term scalar chain + its pooling
    aggs_kernel<<<(NN + 255) / 256, 256>>>(nullptr, v1, 1);                 // 9
    aggs_kernel<<<(NN + 255) / 256, 256>>>(v1, v2, 0);                      // 10
    vpool_kernel<<<(NN + 255) / 256, 256>>>(batch);                         // 11
    // tiny GEMMs and r-vectors
    gemm300_kernel<<<DD, 320>>>(W, W, W2p);                                 // 12
    gemm300_kernel<<<DD, 320>>>(W2p, W, W3p);                               // 13
    rvec_kernel<<<1, 320>>>(b, W);                                          // 14
    // finisher
    final_kernel<<<NG, 320>>>(b, out);                                      // 15
}

// round 6
// speedup vs baseline: 2.6008x; 1.2272x over previous
#include <cuda_runtime.h>
#include <cuda_fp16.h>

#define NN 100000
#define NE 800000
#define DD 300
#define DH 150          // half2 lanes per row
#define ROWB (DH * 4)   // 600 bytes per row
#define L8 75           // uint2 (8B) lanes per row
#define NG 64
#define NB 98           // scan blocks (98 * 1024 >= NN)

// ---------------- scratch (device globals; no allocation allowed) ----------
__device__ int     g_cnt[NN];          // zeroed by scan3 after use (self-resetting)
__device__ int     g_rowptr[NN + 1];
__device__ int     g_wpos[NN];
__device__ int2    g_colp[NE];         // .x = byte offset (src*600), .y = src index
__device__ float   g_dinv[NN];
__device__ int     g_bsum[NB];
__device__ int     g_boff[NB];
__device__ __half2 g_hA[(size_t)NN * DH];   // 60 MB
__device__ __half2 g_hB[(size_t)NN * DH];   // 60 MB
__device__ float   g_v1[NN];
__device__ float   g_v2[NN];
__device__ float   g_Msum[NG * DD];
__device__ float   g_usum[2 * NG];     // [0..63]=Σv1, [64..127]=Σv2 per graph
__device__ int     g_gcnt[NG];
__device__ float   g_T1[NG * DD];
__device__ float   g_T2[NG * DD];

// ---------------- CSR build --------------------------------------------------

__global__ void hist_kernel(const int* __restrict__ ei) {
    int e = blockIdx.x * blockDim.x + threadIdx.x;
    if (e >= NE) return;
    atomicAdd(&g_cnt[ei[NE + e]], 1);   // dst
}

// phase 1: per-block sum of cnt (coalesced) + dinv
__global__ void scan1_kernel() {
    __shared__ int sh[1024];
    int i = blockIdx.x * 1024 + threadIdx.x;
    int c = 0;
    if (i < NN) {
        c = g_cnt[i];
        g_dinv[i] = rsqrtf((float)(c + 1));   // +1 self loop
    }
    sh[threadIdx.x] = c;
    __syncthreads();
    for (int off = 512; off > 0; off >>= 1) {
        if (threadIdx.x < off) sh[threadIdx.x] += sh[threadIdx.x + off];
        __syncthreads();
    }
    if (threadIdx.x == 0) g_bsum[blockIdx.x] = sh[0];
}

// phase 2: tiny exclusive scan of NB block sums; zero accumulators
__global__ void scan2_kernel() {
    __shared__ int sh[NB];
    int tid = threadIdx.x;
    if (tid < NB) sh[tid] = g_bsum[tid];
    __syncthreads();
    if (tid == 0) {
        int run = 0;
        for (int b = 0; b < NB; ++b) { g_boff[b] = run; run += sh[b]; }
        g_rowptr[NN] = run;   // == NE
    }
    for (int i = tid; i < NG * DD; i += blockDim.x) g_Msum[i] = 0.f;
    if (tid < 2 * NG) g_usum[tid] = 0.f;
    if (tid < NG)     g_gcnt[tid] = 0;
}

// phase 3: per-block exclusive scan, coalesced writes; reset cnt
__global__ void scan3_kernel() {
    __shared__ int sh[1024];
    int tid = threadIdx.x;
    int i = blockIdx.x * 1024 + tid;
    int c = (i < NN) ? g_cnt[i] : 0;
    sh[tid] = c;
    __syncthreads();
    for (int off = 1; off < 1024; off <<= 1) {
        int v = (tid >= off) ? sh[tid - off] : 0;
        __syncthreads();
        sh[tid] += v;
        __syncthreads();
    }
    if (i < NN) {
        int excl = g_boff[blockIdx.x] + sh[tid] - c;
        g_rowptr[i] = excl;
        g_wpos[i]   = excl;
        g_cnt[i]    = 0;        // self-reset for next call
    }
}

// fused: CSR column scatter (per edge) + embedding z0 = dinv*(at[a]+wt[w])
#define EDGE_BLOCKS ((NE + 255) / 256)
#define EMB_ITEMS   (NN * DH)
#define EMB_BLOCKS  ((EMB_ITEMS + 255) / 256)
__global__ void scatter_embed_kernel(const int* __restrict__ ei,
                                     const int* __restrict__ x,
                                     const float* __restrict__ at,
                                     const float* __restrict__ wt) {
    if (blockIdx.x < EDGE_BLOCKS) {
        int e = blockIdx.x * 256 + threadIdx.x;
        if (e >= NE) return;
        int dst = ei[NE + e];
        int src = ei[e];
        int pos = atomicAdd(&g_wpos[dst], 1);
        g_colp[pos] = make_int2(src * ROWB, src);
    } else {
        int idx = (blockIdx.x - EDGE_BLOCKS) * 256 + threadIdx.x;
        if (idx >= EMB_ITEMS) return;
        int i = idx / DH;
        int t = idx - i * DH;
        int a  = x[2 * i];
        int w  = x[2 * i + 1];
        float2 va = ((const float2*)at)[a * DH + t];
        float2 vw = ((const float2*)wt)[w * DH + t];
        float di = g_dinv[i];
        float2 z = make_float2(di * (va.x + vw.x), di * (va.y + vw.y));
        g_hA[(size_t)i * DH + t] = __float22half2_rn(z);
    }
}

// one GCN hop on pre-scaled rows (z = dinv .* y), 8B lanes, half2 accumulation.
// last=0: out = dinv^2 * (sum + self)   (z for next hop)
// last=1: out = dinv   * (sum + self)   (true y3 for pooling)
__global__ void agg_step_kernel(const __half2* __restrict__ in,
                                __half2* __restrict__ out, int last) {
    int i = blockIdx.x;
    int t = threadIdx.x;                // 0..95, active t<75
    bool act = t < L8;
    int beg = g_rowptr[i], end = g_rowptr[i + 1];
    const char* base = (const char*)in + t * 8;
    __half2 z = __float2half2_rn(0.f);
    __half2 ax0 = z, ay0 = z, ax1 = z, ay1 = z, ax2 = z, ay2 = z, ax3 = z, ay3 = z;
    int e = beg;
    for (; e + 4 <= end; e += 4) {
        int o0 = g_colp[e].x;
        int o1 = g_colp[e + 1].x;
        int o2 = g_colp[e + 2].x;
        int o3 = g_colp[e + 3].x;
        if (act) {
            uint2 v0 = *(const uint2*)(base + o0);
            uint2 v1 = *(const uint2*)(base + o1);
            uint2 v2 = *(const uint2*)(base + o2);
            uint2 v3 = *(const uint2*)(base + o3);
            ax0 = __hadd2(ax0, *(__half2*)&v0.x); ay0 = __hadd2(ay0, *(__half2*)&v0.y);
            ax1 = __hadd2(ax1, *(__half2*)&v1.x); ay1 = __hadd2(ay1, *(__half2*)&v1.y);
            ax2 = __hadd2(ax2, *(__half2*)&v2.x); ay2 = __hadd2(ay2, *(__half2*)&v2.y);
            ax3 = __hadd2(ax3, *(__half2*)&v3.x); ay3 = __hadd2(ay3, *(__half2*)&v3.y);
        }
    }
    for (; e < end; ++e) {
        int o0 = g_colp[e].x;
        if (act) {
            uint2 v0 = *(const uint2*)(base + o0);
            ax0 = __hadd2(ax0, *(__half2*)&v0.x); ay0 = __hadd2(ay0, *(__half2*)&v0.y);
        }
    }
    if (act) {
        uint2 sv = *(const uint2*)(base + i * ROWB);
        float2 sx = __half22float2(*(__half2*)&sv.x);
        float2 sy = __half22float2(*(__half2*)&sv.y);
        float2 fx0 = __half22float2(ax0), fx1 = __half22float2(ax1);
        float2 fx2 = __half22float2(ax2), fx3 = __half22float2(ax3);
        float2 fy0 = __half22float2(ay0), fy1 = __half22float2(ay1);
        float2 fy2 = __half22float2(ay2), fy3 = __half22float2(ay3);
        float di = g_dinv[i];
        float f = last ? di : di * di;
        float2 rx = make_float2(f * ((fx0.x + fx1.x) + (fx2.x + fx3.x) + sx.x),
                                f * ((fx0.y + fx1.y) + (fx2.y + fx3.y) + sx.y));
        float2 ry = make_float2(f * ((fy0.x + fy1.x) + (fy2.x + fy3.x) + sy.x),
                                f * ((fy0.y + fy1.y) + (fy2.y + fy3.y) + sy.y));
        uint2 o;
        *(__half2*)&o.x = __float22half2_rn(rx);
        *(__half2*)&o.y = __float22half2_rn(ry);
        *(uint2*)((char*)out + i * ROWB + t * 8) = o;
    }
}

// scalar aggregation for the bias terms; ones=1 -> input is all-ones
__global__ void aggs_kernel(const float* __restrict__ vin, float* __restrict__ vout, int ones) {
    int i = blockIdx.x * blockDim.x + threadIdx.x;
    if (i >= NN) return;
    int beg = g_rowptr[i];
    int end = g_rowptr[i + 1];
    float sum = 0.f;
    for (int e = beg; e < end; ++e) {
        int s = g_colp[e].y;
        float w = g_dinv[s];
        sum += ones ? w : w * vin[s];
    }
    float di = g_dinv[i];
    float self = ones ? 1.f : vin[i];
    vout[i] = di * (sum + di * self);
}

// mean-pool partial sums (batch sorted): run-length accumulate, atomic flush; 8B lanes
__global__ void pool_kernel(const __half2* __restrict__ h, const int* __restrict__ batch) {
    const int CH = 128;
    int n0 = blockIdx.x * CH;
    int n1 = n0 + CH; if (n1 > NN) n1 = NN;
    int t = threadIdx.x;                // 0..95, active t<75
    bool act = t < L8;
    const char* base = (const char*)h + t * 8;
    float2 ax = make_float2(0.f, 0.f);
    float2 ay = make_float2(0.f, 0.f);
    int cur = batch[n0];
    for (int n = n0; n < n1; ++n) {
        int g = batch[n];
        if (g != cur) {
            if (act) {
                atomicAdd(&g_Msum[cur * DD + 4 * t],     ax.x);
                atomicAdd(&g_Msum[cur * DD + 4 * t + 1], ax.y);
                atomicAdd(&g_Msum[cur * DD + 4 * t + 2], ay.x);
                atomicAdd(&g_Msum[cur * DD + 4 * t + 3], ay.y);
            }
            ax = make_float2(0.f, 0.f);
            ay = make_float2(0.f, 0.f);
            cur = g;
        }
        if (act) {
            uint2 v = *(const uint2*)(base + n * ROWB);
            float2 vx = __half22float2(*(__half2*)&v.x);
            float2 vy = __half22float2(*(__half2*)&v.y);
            ax.x += vx.x; ax.y += vx.y;
            ay.x += vy.x; ay.y += vy.y;
        }
    }
    if (act) {
        atomicAdd(&g_Msum[cur * DD + 4 * t],     ax.x);
        atomicAdd(&g_Msum[cur * DD + 4 * t + 1], ax.y);
        atomicAdd(&g_Msum[cur * DD + 4 * t + 2], ay.x);
        atomicAdd(&g_Msum[cur * DD + 4 * t + 3], ay.y);
    }
}

__global__ void vpool_kernel(const int* __restrict__ batch) {
    int i = blockIdx.x * blockDim.x + threadIdx.x;
    if (i >= NN) return;
    int bg = batch[i];
    atomicAdd(&g_gcnt[bg], 1);
    atomicAdd(&g_usum[bg], g_v1[i]);
    atomicAdd(&g_usum[NG + bg], g_v2[i]);
}

// epilogue GEMM step: out[g] = in[g] @ W  (+ coef[g]*b   when finalize=0)
//                     out[g] = in[g]@W/max(cnt,1) + (cnt>0)*b   when finalize=1
__global__ void mg_kernel(const float* __restrict__ in, float* __restrict__ outp,
                          const float* __restrict__ W, const float* __restrict__ bvec,
                          const float* __restrict__ coef, int finalize) {
    int g = blockIdx.x;
    int c = threadIdx.x;
    __shared__ float arow[DD];
    for (int k = c; k < DD; k += 320) arow[k] = in[g * DD + k];
    __syncthreads();
    if (c >= DD) return;
    float acc = 0.f;
    #pragma unroll 4
    for (int k = 0; k < DD; ++k) acc += arow[k] * W[k * DD + c];
    if (!finalize) {
        outp[g * DD + c] = acc + coef[g] * bvec[c];
    } else {
        int cnt = g_gcnt[g];
        float denom = (cnt > 0) ? (float)cnt : 1.f;
        float r = acc / denom;
        if (cnt > 0) r += bvec[c];
        outp[g * DD + c] = r;
    }
}

// ---------------- launch ----------------------------------------------------

extern "C" void kernel_launch(void* const* d_in, const int* in_sizes, int n_in,
                              void* d_out, int out_size) {
    const int*   x     = (const int*)d_in[0];     // [N,2]
    const int*   ei    = (const int*)d_in[1];     // [2,E]
    const int*   batch = (const int*)d_in[2];     // [N]
    const float* at    = (const float*)d_in[3];   // [41,300]
    const float* wt    = (const float*)d_in[4];   // [10000,300]
    const float* W     = (const float*)d_in[5];   // [300,300]
    const float* b     = (const float*)d_in[6];   // [300]
    float* out = (float*)d_out;

    __half2 *hA, *hB;
    float *v1, *v2, *T1, *T2, *Msum, *usum;
    cudaGetSymbolAddress((void**)&hA,   g_hA);
    cudaGetSymbolAddress((void**)&hB,   g_hB);
    cudaGetSymbolAddress((void**)&v1,   g_v1);
    cudaGetSymbolAddress((void**)&v2,   g_v2);
    cudaGetSymbolAddress((void**)&T1,   g_T1);
    cudaGetSymbolAddress((void**)&T2,   g_T2);
    cudaGetSymbolAddress((void**)&Msum, g_Msum);
    cudaGetSymbolAddress((void**)&usum, g_usum);

    // CSR build (coalesced 3-phase scan; g_cnt self-resetting)
    hist_kernel<<<(NE + 255) / 256, 256>>>(ei);                             // 0
    scan1_kernel<<<NB, 1024>>>();                                           // 1
    scan2_kernel<<<1, 256>>>();                                             // 2
    scan3_kernel<<<NB, 1024>>>();                                           // 3
    scatter_embed_kernel<<<EDGE_BLOCKS + EMB_BLOCKS, 256>>>(ei, x, at, wt); // 4
    // three hops (8B lanes)
    agg_step_kernel<<<NN, 96>>>(hA, hB, 0);                                 // 5
    agg_step_kernel<<<NN, 96>>>(hB, hA, 0);                                 // 6
    agg_step_kernel<<<NN, 96>>>(hA, hB, 1);                                 // 7 -> y3 in hB
    // pooling of y3
    pool_kernel<<<(NN + 127) / 128, 96>>>(hB, batch);                       // 8
    // bias-term scalar chain + its pooling
    aggs_kernel<<<(NN + 255) / 256, 256>>>(nullptr, v1, 1);                 // 9
    aggs_kernel<<<(NN + 255) / 256, 256>>>(v1, v2, 0);                      // 10
    vpool_kernel<<<(NN + 255) / 256, 256>>>(batch);                         // 11
    // epilogue: ((Msum@W + u2⊗b)@W + u1⊗b)@W, then /cnt + b
    mg_kernel<<<NG, 320>>>(Msum, T1, W, b, usum + NG, 0);                   // 12
    mg_kernel<<<NG, 320>>>(T1,   T2, W, b, usum,      0);                   // 13
    mg_kernel<<<NG, 320>>>(T2,  out, W, b, usum,      1);                   // 14
}

// round 7
// speedup vs baseline: 3.3261x; 1.2789x over previous
#include <cuda_runtime.h>
#include <cuda_fp16.h>

#define NN 100000
#define NE 800000
#define DD 300
#define ROWB 608        // padded row bytes (38 * 16)
#define RH2 152         // half2 lanes per padded row
#define L16 38          // uint4 lanes per row
#define L8 75           // real 8B lanes (600B) for pooling
#define NG 64
#define NB 98           // scan blocks (98 * 1024 >= NN)

// ---------------- scratch (device globals; no allocation allowed) ----------
__device__ int     g_cnt[NN];          // zeroed by scan3 after use (self-resetting)
__device__ int     g_rowptr[NN + 1];
__device__ int     g_wpos[NN];
__device__ int2    g_colp[NE];         // .x = byte offset (src*608), .y = src index
__device__ float   g_dinv[NN];
__device__ int     g_bsum[NB];
__device__ int     g_boff[NB];
__device__ __half2 g_hA[(size_t)NN * RH2];   // 60.8 MB
__device__ __half2 g_hB[(size_t)NN * RH2];   // 60.8 MB
__device__ float   g_v1[NN];
__device__ float   g_v2[NN];
__device__ float   g_Msum[NG * DD];
__device__ float   g_usum[2 * NG];     // [0..63]=Σv1, [64..127]=Σv2 per graph
__device__ int     g_gcnt[NG];
__device__ float   g_T1[NG * DD];
__device__ float   g_T2[NG * DD];

// ---------------- CSR build --------------------------------------------------

__global__ void hist_kernel(const int* __restrict__ ei) {
    int e = blockIdx.x * blockDim.x + threadIdx.x;
    if (e >= NE) return;
    atomicAdd(&g_cnt[ei[NE + e]], 1);   // dst
}

__global__ void scan1_kernel() {
    __shared__ int sh[1024];
    int i = blockIdx.x * 1024 + threadIdx.x;
    int c = 0;
    if (i < NN) {
        c = g_cnt[i];
        g_dinv[i] = rsqrtf((float)(c + 1));   // +1 self loop
    }
    sh[threadIdx.x] = c;
    __syncthreads();
    for (int off = 512; off > 0; off >>= 1) {
        if (threadIdx.x < off) sh[threadIdx.x] += sh[threadIdx.x + off];
        __syncthreads();
    }
    if (threadIdx.x == 0) g_bsum[blockIdx.x] = sh[0];
}

__global__ void scan2_kernel() {
    __shared__ int sh[NB];
    int tid = threadIdx.x;
    if (tid < NB) sh[tid] = g_bsum[tid];
    __syncthreads();
    if (tid == 0) {
        int run = 0;
        for (int b = 0; b < NB; ++b) { g_boff[b] = run; run += sh[b]; }
        g_rowptr[NN] = run;   // == NE
    }
    for (int i = tid; i < NG * DD; i += blockDim.x) g_Msum[i] = 0.f;
    if (tid < 2 * NG) g_usum[tid] = 0.f;
    if (tid < NG)     g_gcnt[tid] = 0;
}

__global__ void scan3_kernel() {
    __shared__ int sh[1024];
    int tid = threadIdx.x;
    int i = blockIdx.x * 1024 + tid;
    int c = (i < NN) ? g_cnt[i] : 0;
    sh[tid] = c;
    __syncthreads();
    for (int off = 1; off < 1024; off <<= 1) {
        int v = (tid >= off) ? sh[tid - off] : 0;
        __syncthreads();
        sh[tid] += v;
        __syncthreads();
    }
    if (i < NN) {
        int excl = g_boff[blockIdx.x] + sh[tid] - c;
        g_rowptr[i] = excl;
        g_wpos[i]   = excl;
        g_cnt[i]    = 0;        // self-reset for next call
    }
}

// fused: CSR column scatter (per edge) + embedding z0 = dinv*(at[a]+wt[w])
// padding lanes (t >= 150) are written as exact zeros.
#define EDGE_BLOCKS ((NE + 255) / 256)
#define EMB_ITEMS   (NN * RH2)
#define EMB_BLOCKS  ((EMB_ITEMS + 255) / 256)
__global__ void scatter_embed_kernel(const int* __restrict__ ei,
                                     const int* __restrict__ x,
                                     const float* __restrict__ at,
                                     const float* __restrict__ wt) {
    if (blockIdx.x < EDGE_BLOCKS) {
        int e = blockIdx.x * 256 + threadIdx.x;
        if (e >= NE) return;
        int dst = ei[NE + e];
        int src = ei[e];
        int pos = atomicAdd(&g_wpos[dst], 1);
        g_colp[pos] = make_int2(src * ROWB, src);
    } else {
        int idx = (blockIdx.x - EDGE_BLOCKS) * 256 + threadIdx.x;
        if (idx >= EMB_ITEMS) return;
        int i = idx / RH2;
        int t = idx - i * RH2;
        __half2 r = __float2half2_rn(0.f);
        if (t < DD / 2) {
            int a  = x[2 * i];
            int w  = x[2 * i + 1];
            float2 va = ((const float2*)at)[a * (DD / 2) + t];
            float2 vw = ((const float2*)wt)[w * (DD / 2) + t];
            float di = g_dinv[i];
            r = __float22half2_rn(make_float2(di * (va.x + vw.x), di * (va.y + vw.y)));
        }
        g_hA[(size_t)i * RH2 + t] = r;
    }
}

// one GCN hop on pre-scaled rows (z = dinv .* y), 16B lanes, half2 accumulation.
// last=0: out = dinv^2 * (sum + self)   (z for next hop)
// last=1: out = dinv   * (sum + self)   (true y3 for pooling)
__global__ void agg_step_kernel(const __half2* __restrict__ in,
                                __half2* __restrict__ out, int last) {
    int i = blockIdx.x;
    int t = threadIdx.x;                // 0..63, active t<38
    bool act = t < L16;
    int beg = g_rowptr[i], end = g_rowptr[i + 1];
    const char* base = (const char*)in + t * 16;
    __half2 z = __float2half2_rn(0.f);
    __half2 a0 = z, a1 = z, a2 = z, a3 = z;   // set 0
    __half2 b0 = z, b1 = z, b2 = z, b3 = z;   // set 1
    int e = beg;
    // align e to even for int4 offset loads
    if (e < end && (e & 1)) {
        int o = g_colp[e].x;
        if (act) {
            uint4 v = *(const uint4*)(base + o);
            a0 = __hadd2(a0, *(__half2*)&v.x); a1 = __hadd2(a1, *(__half2*)&v.y);
            a2 = __hadd2(a2, *(__half2*)&v.z); a3 = __hadd2(a3, *(__half2*)&v.w);
        }
        ++e;
    }
    for (; e + 4 <= end; e += 4) {
        int4 p0 = *(const int4*)&g_colp[e];       // (.x,.z) = offsets of edges e,e+1
        int4 p1 = *(const int4*)&g_colp[e + 2];
        if (act) {
            uint4 v0 = *(const uint4*)(base + p0.x);
            uint4 v1 = *(const uint4*)(base + p0.z);
            uint4 v2 = *(const uint4*)(base + p1.x);
            uint4 v3 = *(const uint4*)(base + p1.z);
            a0 = __hadd2(a0, *(__half2*)&v0.x); a1 = __hadd2(a1, *(__half2*)&v0.y);
            a2 = __hadd2(a2, *(__half2*)&v0.z); a3 = __hadd2(a3, *(__half2*)&v0.w);
            b0 = __hadd2(b0, *(__half2*)&v1.x); b1 = __hadd2(b1, *(__half2*)&v1.y);
            b2 = __hadd2(b2, *(__half2*)&v1.z); b3 = __hadd2(b3, *(__half2*)&v1.w);
            a0 = __hadd2(a0, *(__half2*)&v2.x); a1 = __hadd2(a1, *(__half2*)&v2.y);
            a2 = __hadd2(a2, *(__half2*)&v2.z); a3 = __hadd2(a3, *(__half2*)&v2.w);
            b0 = __hadd2(b0, *(__half2*)&v3.x); b1 = __hadd2(b1, *(__half2*)&v3.y);
            b2 = __hadd2(b2, *(__half2*)&v3.z); b3 = __hadd2(b3, *(__half2*)&v3.w);
        }
    }
    for (; e < end; ++e) {
        int o = g_colp[e].x;
        if (act) {
            uint4 v = *(const uint4*)(base + o);
            a0 = __hadd2(a0, *(__half2*)&v.x); a1 = __hadd2(a1, *(__half2*)&v.y);
            a2 = __hadd2(a2, *(__half2*)&v.z); a3 = __hadd2(a3, *(__half2*)&v.w);
        }
    }
    if (act) {
        uint4 sv = *(const uint4*)(base + i * ROWB);
        float di = g_dinv[i];
        float f = last ? di : di * di;
        float2 s0 = __half22float2(*(__half2*)&sv.x);
        float2 s1 = __half22float2(*(__half2*)&sv.y);
        float2 s2 = __half22float2(*(__half2*)&sv.z);
        float2 s3 = __half22float2(*(__half2*)&sv.w);
        float2 fa0 = __half22float2(a0), fb0 = __half22float2(b0);
        float2 fa1 = __half22float2(a1), fb1 = __half22float2(b1);
        float2 fa2 = __half22float2(a2), fb2 = __half22float2(b2);
        float2 fa3 = __half22float2(a3), fb3 = __half22float2(b3);
        uint4 o;
        float2 r0 = make_float2(f * (fa0.x + fb0.x + s0.x), f * (fa0.y + fb0.y + s0.y));
        float2 r1 = make_float2(f * (fa1.x + fb1.x + s1.x), f * (fa1.y + fb1.y + s1.y));
        float2 r2 = make_float2(f * (fa2.x + fb2.x + s2.x), f * (fa2.y + fb2.y + s2.y));
        float2 r3 = make_float2(f * (fa3.x + fb3.x + s3.x), f * (fa3.y + fb3.y + s3.y));
        *(__half2*)&o.x = __float22half2_rn(r0);
        *(__half2*)&o.y = __float22half2_rn(r1);
        *(__half2*)&o.z = __float22half2_rn(r2);
        *(__half2*)&o.w = __float22half2_rn(r3);
        *(uint4*)((char*)out + i * ROWB + t * 16) = o;
    }
}

// scalar aggregation pass 1: v1 = A*1
__global__ void aggs1_kernel() {
    int i = blockIdx.x * blockDim.x + threadIdx.x;
    if (i >= NN) return;
    int beg = g_rowptr[i], end = g_rowptr[i + 1];
    float sum = 0.f;
    for (int e = beg; e < end; ++e) sum += g_dinv[g_colp[e].y];
    float di = g_dinv[i];
    g_v1[i] = di * (sum + di);
}

// pass 2 fused with vector pooling: v2 = A*v1; accumulate gcnt, Σv1, Σv2 per graph
__global__ void aggs2_kernel(const int* __restrict__ batch) {
    int i = blockIdx.x * blockDim.x + threadIdx.x;
    if (i >= NN) return;
    int beg = g_rowptr[i], end = g_rowptr[i + 1];
    float sum = 0.f;
    for (int e = beg; e < end; ++e) {
        int s = g_colp[e].y;
        sum += g_dinv[s] * g_v1[s];
    }
    float di = g_dinv[i];
    float v1 = g_v1[i];
    float v2 = di * (sum + di * v1);
    int bg = batch[i];
    atomicAdd(&g_gcnt[bg], 1);
    atomicAdd(&g_usum[bg], v1);
    atomicAdd(&g_usum[NG + bg], v2);
}

// mean-pool partial sums (batch sorted): run-length accumulate, atomic flush; 8B lanes
__global__ void pool_kernel(const __half2* __restrict__ h, const int* __restrict__ batch) {
    const int CH = 64;
    int n0 = blockIdx.x * CH;
    int n1 = n0 + CH; if (n1 > NN) n1 = NN;
    int t = threadIdx.x;                // 0..95, active t<75
    bool act = t < L8;
    const char* base = (const char*)h + t * 8;
    float2 ax = make_float2(0.f, 0.f);
    float2 ay = make_float2(0.f, 0.f);
    int cur = batch[n0];
    for (int n = n0; n < n1; ++n) {
        int g = batch[n];
        if (g != cur) {
            if (act) {
                atomicAdd(&g_Msum[cur * DD + 4 * t],     ax.x);
                atomicAdd(&g_Msum[cur * DD + 4 * t + 1], ax.y);
                atomicAdd(&g_Msum[cur * DD + 4 * t + 2], ay.x);
                atomicAdd(&g_Msum[cur * DD + 4 * t + 3], ay.y);
            }
            ax = make_float2(0.f, 0.f);
            ay = make_float2(0.f, 0.f);
            cur = g;
        }
        if (act) {
            uint2 v = *(const uint2*)(base + (size_t)n * ROWB);
            float2 vx = __half22float2(*(__half2*)&v.x);
            float2 vy = __half22float2(*(__half2*)&v.y);
            ax.x += vx.x; ax.y += vx.y;
            ay.x += vy.x; ay.y += vy.y;
        }
    }
    if (act) {
        atomicAdd(&g_Msum[cur * DD + 4 * t],     ax.x);
        atomicAdd(&g_Msum[cur * DD + 4 * t + 1], ax.y);
        atomicAdd(&g_Msum[cur * DD + 4 * t + 2], ay.x);
        atomicAdd(&g_Msum[cur * DD + 4 * t + 3], ay.y);
    }
}

// epilogue GEMM step: out[g] = in[g]@W + coef[g]*b          (finalize=0)
//                     out[g] = in[g]@W/max(cnt,1)+(cnt>0)*b (finalize=1)
__global__ void mg_kernel(const float* __restrict__ in, float* __restrict__ outp,
                          const float* __restrict__ W, const float* __restrict__ bvec,
                          const float* __restrict__ coef, int finalize) {
    int g = blockIdx.x;
    int c = threadIdx.x;
    __shared__ float arow[DD];
    for (int k = c; k < DD; k += 320) arow[k] = in[g * DD + k];
    __syncthreads();
    if (c >= DD) return;
    float acc = 0.f;
    #pragma unroll 4
    for (int k = 0; k < DD; ++k) acc += arow[k] * W[k * DD + c];
    if (!finalize) {
        outp[g * DD + c] = acc + coef[g] * bvec[c];
    } else {
        int cnt = g_gcnt[g];
        float denom = (cnt > 0) ? (float)cnt : 1.f;
        float r = acc / denom;
        if (cnt > 0) r += bvec[c];
        outp[g * DD + c] = r;
    }
}

// ---------------- launch ----------------------------------------------------

extern "C" void kernel_launch(void* const* d_in, const int* in_sizes, int n_in,
                              void* d_out, int out_size) {
    const int*   x     = (const int*)d_in[0];     // [N,2]
    const int*   ei    = (const int*)d_in[1];     // [2,E]
    const int*   batch = (const int*)d_in[2];     // [N]
    const float* at    = (const float*)d_in[3];   // [41,300]
    const float* wt    = (const float*)d_in[4];   // [10000,300]
    const float* W     = (const float*)d_in[5];   // [300,300]
    const float* b     = (const float*)d_in[6];   // [300]
    float* out = (float*)d_out;

    __half2 *hA, *hB;
    float *T1, *T2, *Msum, *usum;
    cudaGetSymbolAddress((void**)&hA,   g_hA);
    cudaGetSymbolAddress((void**)&hB,   g_hB);
    cudaGetSymbolAddress((void**)&T1,   g_T1);
    cudaGetSymbolAddress((void**)&T2,   g_T2);
    cudaGetSymbolAddress((void**)&Msum, g_Msum);
    cudaGetSymbolAddress((void**)&usum, g_usum);

    // CSR build (coalesced 3-phase scan; g_cnt self-resetting)
    hist_kernel<<<(NE + 255) / 256, 256>>>(ei);                             // 0
    scan1_kernel<<<NB, 1024>>>();                                           // 1
    scan2_kernel<<<1, 256>>>();                                             // 2
    scan3_kernel<<<NB, 1024>>>();                                           // 3
    scatter_embed_kernel<<<EDGE_BLOCKS + EMB_BLOCKS, 256>>>(ei, x, at, wt); // 4
    // three hops (16B lanes, 2 warps per node)
    agg_step_kernel<<<NN, 64>>>(hA, hB, 0);                                 // 5
    agg_step_kernel<<<NN, 64>>>(hB, hA, 0);                                 // 6
    agg_step_kernel<<<NN, 64>>>(hA, hB, 1);                                 // 7 -> y3 in hB
    // pooling of y3
    pool_kernel<<<(NN + 63) / 64, 96>>>(hB, batch);                         // 8
    // bias-term scalar chain (pass 2 fused with vector pooling)
    aggs1_kernel<<<(NN + 255) / 256, 256>>>();                              // 9
    aggs2_kernel<<<(NN + 255) / 256, 256>>>(batch);                         // 10
    // epilogue: ((Msum@W + u2⊗b)@W + u1⊗b)@W, then /cnt + b
    mg_kernel<<<NG, 320>>>(Msum, T1, W, b, usum + NG, 0);                   // 11
    mg_kernel<<<NG, 320>>>(T1,   T2, W, b, usum,      0);                   // 12
    mg_kernel<<<NG, 320>>>(T2,  out, W, b, usum,      1);                   // 13
}

// round 8
// speedup vs baseline: 3.3290x; 1.0009x over previous
#include <cuda_runtime.h>
#include <cuda_fp16.h>

#define NN 100000
#define NE 800000
#define DD 300
#define ROWB 608        // padded row bytes (38 * 16)
#define RH2 152         // half2 lanes per padded row
#define L16 38          // uint4 lanes per row
#define L8 75           // real 8B lanes (600B) for pooling
#define NG 64
#define NB 98           // scan blocks (98 * 1024 >= NN)

// ---------------- scratch (device globals; no allocation allowed) ----------
__device__ int     g_cnt[NN];          // zeroed by scan3 after use (self-resetting)
__device__ int     g_rowptr[NN + 1];
__device__ int     g_wpos[NN];
__device__ int2    g_colp[NE];         // .x = byte offset (src*608), .y = src index
__device__ float   g_dinv[NN];
__device__ int     g_bsum[NB];
__device__ int     g_boff[NB];
__device__ __half2 g_hA[(size_t)NN * RH2];   // 60.8 MB
__device__ __half2 g_hB[(size_t)NN * RH2];   // 60.8 MB
__device__ float   g_v1[NN];
__device__ float   g_v2[NN];
__device__ float   g_Msum[NG * DD];
__device__ float   g_usum[2 * NG];     // [0..63]=Σv1, [64..127]=Σv2 per graph
__device__ int     g_gcnt[NG];
__device__ float   g_T1[NG * DD];
__device__ float   g_T2[NG * DD];

// ---------------- CSR build --------------------------------------------------

__global__ void hist_kernel(const int* __restrict__ ei) {
    int e = blockIdx.x * blockDim.x + threadIdx.x;
    if (e >= NE) return;
    atomicAdd(&g_cnt[ei[NE + e]], 1);   // dst
}

__global__ void scan1_kernel() {
    __shared__ int sh[1024];
    int i = blockIdx.x * 1024 + threadIdx.x;
    int c = 0;
    if (i < NN) {
        c = g_cnt[i];
        g_dinv[i] = rsqrtf((float)(c + 1));   // +1 self loop
    }
    sh[threadIdx.x] = c;
    __syncthreads();
    for (int off = 512; off > 0; off >>= 1) {
        if (threadIdx.x < off) sh[threadIdx.x] += sh[threadIdx.x + off];
        __syncthreads();
    }
    if (threadIdx.x == 0) g_bsum[blockIdx.x] = sh[0];
}

__global__ void scan2_kernel() {
    __shared__ int sh[NB];
    int tid = threadIdx.x;
    if (tid < NB) sh[tid] = g_bsum[tid];
    __syncthreads();
    if (tid == 0) {
        int run = 0;
        for (int b = 0; b < NB; ++b) { g_boff[b] = run; run += sh[b]; }
        g_rowptr[NN] = run;   // == NE
    }
    for (int i = tid; i < NG * DD; i += blockDim.x) g_Msum[i] = 0.f;
    if (tid < 2 * NG) g_usum[tid] = 0.f;
    if (tid < NG)     g_gcnt[tid] = 0;
}

__global__ void scan3_kernel() {
    __shared__ int sh[1024];
    int tid = threadIdx.x;
    int i = blockIdx.x * 1024 + tid;
    int c = (i < NN) ? g_cnt[i] : 0;
    sh[tid] = c;
    __syncthreads();
    for (int off = 1; off < 1024; off <<= 1) {
        int v = (tid >= off) ? sh[tid - off] : 0;
        __syncthreads();
        sh[tid] += v;
        __syncthreads();
    }
    if (i < NN) {
        int excl = g_boff[blockIdx.x] + sh[tid] - c;
        g_rowptr[i] = excl;
        g_wpos[i]   = excl;
        g_cnt[i]    = 0;        // self-reset for next call
    }
}

// fused: CSR column scatter (per edge) + embedding z0 = dinv*(at[a]+wt[w])
// padding lanes (t >= 150) are written as exact zeros.
#define EDGE_BLOCKS ((NE + 255) / 256)
#define EMB_ITEMS   (NN * RH2)
#define EMB_BLOCKS  ((EMB_ITEMS + 255) / 256)
__global__ void scatter_embed_kernel(const int* __restrict__ ei,
                                     const int* __restrict__ x,
                                     const float* __restrict__ at,
                                     const float* __restrict__ wt) {
    if (blockIdx.x < EDGE_BLOCKS) {
        int e = blockIdx.x * 256 + threadIdx.x;
        if (e >= NE) return;
        int dst = ei[NE + e];
        int src = ei[e];
        int pos = atomicAdd(&g_wpos[dst], 1);
        g_colp[pos] = make_int2(src * ROWB, src);
    } else {
        int idx = (blockIdx.x - EDGE_BLOCKS) * 256 + threadIdx.x;
        if (idx >= EMB_ITEMS) return;
        int i = idx / RH2;
        int t = idx - i * RH2;
        __half2 r = __float2half2_rn(0.f);
        if (t < DD / 2) {
            int a  = x[2 * i];
            int w  = x[2 * i + 1];
            float2 va = ((const float2*)at)[a * (DD / 2) + t];
            float2 vw = ((const float2*)wt)[w * (DD / 2) + t];
            float di = g_dinv[i];
            r = __float22half2_rn(make_float2(di * (va.x + vw.x), di * (va.y + vw.y)));
        }
        g_hA[(size_t)i * RH2 + t] = r;
    }
}

// one GCN hop on pre-scaled rows (z = dinv .* y), 16B lanes, half2 accumulation.
// last=0: out = dinv^2 * (sum + self)   (z for next hop)
// last=1: out = dinv   * (sum + self)   (true y3 for pooling)
__global__ void agg_step_kernel(const __half2* __restrict__ in,
                                __half2* __restrict__ out, int last) {
    int i = blockIdx.x;
    int t = threadIdx.x;                // 0..63, active t<38
    bool act = t < L16;
    int beg = g_rowptr[i], end = g_rowptr[i + 1];
    const char* base = (const char*)in + t * 16;
    __half2 z = __float2half2_rn(0.f);
    __half2 a0 = z, a1 = z, a2 = z, a3 = z;   // set 0
    __half2 b0 = z, b1 = z, b2 = z, b3 = z;   // set 1
    int e = beg;
    // align e to even for int4 offset loads
    if (e < end && (e & 1)) {
        int o = g_colp[e].x;
        if (act) {
            uint4 v = *(const uint4*)(base + o);
            a0 = __hadd2(a0, *(__half2*)&v.x); a1 = __hadd2(a1, *(__half2*)&v.y);
            a2 = __hadd2(a2, *(__half2*)&v.z); a3 = __hadd2(a3, *(__half2*)&v.w);
        }
        ++e;
    }
    for (; e + 4 <= end; e += 4) {
        int4 p0 = *(const int4*)&g_colp[e];       // (.x,.z) = offsets of edges e,e+1
        int4 p1 = *(const int4*)&g_colp[e + 2];
        if (act) {
            uint4 v0 = *(const uint4*)(base + p0.x);
            uint4 v1 = *(const uint4*)(base + p0.z);
            uint4 v2 = *(const uint4*)(base + p1.x);
            uint4 v3 = *(const uint4*)(base + p1.z);
            a0 = __hadd2(a0, *(__half2*)&v0.x); a1 = __hadd2(a1, *(__half2*)&v0.y);
            a2 = __hadd2(a2, *(__half2*)&v0.z); a3 = __hadd2(a3, *(__half2*)&v0.w);
            b0 = __hadd2(b0, *(__half2*)&v1.x); b1 = __hadd2(b1, *(__half2*)&v1.y);
            b2 = __hadd2(b2, *(__half2*)&v1.z); b3 = __hadd2(b3, *(__half2*)&v1.w);
            a0 = __hadd2(a0, *(__half2*)&v2.x); a1 = __hadd2(a1, *(__half2*)&v2.y);
            a2 = __hadd2(a2, *(__half2*)&v2.z); a3 = __hadd2(a3, *(__half2*)&v2.w);
            b0 = __hadd2(b0, *(__half2*)&v3.x); b1 = __hadd2(b1, *(__half2*)&v3.y);
            b2 = __hadd2(b2, *(__half2*)&v3.z); b3 = __hadd2(b3, *(__half2*)&v3.w);
        }
    }
    for (; e < end; ++e) {
        int o = g_colp[e].x;
        if (act) {
            uint4 v = *(const uint4*)(base + o);
            a0 = __hadd2(a0, *(__half2*)&v.x); a1 = __hadd2(a1, *(__half2*)&v.y);
            a2 = __hadd2(a2, *(__half2*)&v.z); a3 = __hadd2(a3, *(__half2*)&v.w);
        }
    }
    if (act) {
        uint4 sv = *(const uint4*)(base + i * ROWB);
        float di = g_dinv[i];
        float f = last ? di : di * di;
        float2 s0 = __half22float2(*(__half2*)&sv.x);
        float2 s1 = __half22float2(*(__half2*)&sv.y);
        float2 s2 = __half22float2(*(__half2*)&sv.z);
        float2 s3 = __half22float2(*(__half2*)&sv.w);
        float2 fa0 = __half22float2(a0), fb0 = __half22float2(b0);
        float2 fa1 = __half22float2(a1), fb1 = __half22float2(b1);
        float2 fa2 = __half22float2(a2), fb2 = __half22float2(b2);
        float2 fa3 = __half22float2(a3), fb3 = __half22float2(b3);
        uint4 o;
        float2 r0 = make_float2(f * (fa0.x + fb0.x + s0.x), f * (fa0.y + fb0.y + s0.y));
        float2 r1 = make_float2(f * (fa1.x + fb1.x + s1.x), f * (fa1.y + fb1.y + s1.y));
        float2 r2 = make_float2(f * (fa2.x + fb2.x + s2.x), f * (fa2.y + fb2.y + s2.y));
        float2 r3 = make_float2(f * (fa3.x + fb3.x + s3.x), f * (fa3.y + fb3.y + s3.y));
        *(__half2*)&o.x = __float22half2_rn(r0);
        *(__half2*)&o.y = __float22half2_rn(r1);
        *(__half2*)&o.z = __float22half2_rn(r2);
        *(__half2*)&o.w = __float22half2_rn(r3);
        *(uint4*)((char*)out + i * ROWB + t * 16) = o;
    }
}

// scalar aggregation pass 1: v1 = A*1
__global__ void aggs1_kernel() {
    int i = blockIdx.x * blockDim.x + threadIdx.x;
    if (i >= NN) return;
    int beg = g_rowptr[i], end = g_rowptr[i + 1];
    float sum = 0.f;
    for (int e = beg; e < end; ++e) sum += g_dinv[g_colp[e].y];
    float di = g_dinv[i];
    g_v1[i] = di * (sum + di);
}

// pass 2 fused with vector pooling: v2 = A*v1; accumulate gcnt, Σv1, Σv2 per graph
__global__ void aggs2_kernel(const int* __restrict__ batch) {
    int i = blockIdx.x * blockDim.x + threadIdx.x;
    if (i >= NN) return;
    int beg = g_rowptr[i], end = g_rowptr[i + 1];
    float sum = 0.f;
    for (int e = beg; e < end; ++e) {
        int s = g_colp[e].y;
        sum += g_dinv[s] * g_v1[s];
    }
    float di = g_dinv[i];
    float v1 = g_v1[i];
    float v2 = di * (sum + di * v1);
    int bg = batch[i];
    atomicAdd(&g_gcnt[bg], 1);
    atomicAdd(&g_usum[bg], v1);
    atomicAdd(&g_usum[NG + bg], v2);
}

// mean-pool partial sums (batch sorted): run-length accumulate, atomic flush; 8B lanes
__global__ void pool_kernel(const __half2* __restrict__ h, const int* __restrict__ batch) {
    const int CH = 64;
    int n0 = blockIdx.x * CH;
    int n1 = n0 + CH; if (n1 > NN) n1 = NN;
    int t = threadIdx.x;                // 0..95, active t<75
    bool act = t < L8;
    const char* base = (const char*)h + t * 8;
    float2 ax = make_float2(0.f, 0.f);
    float2 ay = make_float2(0.f, 0.f);
    int cur = batch[n0];
    for (int n = n0; n < n1; ++n) {
        int g = batch[n];
        if (g != cur) {
            if (act) {
                atomicAdd(&g_Msum[cur * DD + 4 * t],     ax.x);
                atomicAdd(&g_Msum[cur * DD + 4 * t + 1], ax.y);
                atomicAdd(&g_Msum[cur * DD + 4 * t + 2], ay.x);
                atomicAdd(&g_Msum[cur * DD + 4 * t + 3], ay.y);
            }
            ax = make_float2(0.f, 0.f);
            ay = make_float2(0.f, 0.f);
            cur = g;
        }
        if (act) {
            uint2 v = *(const uint2*)(base + (size_t)n * ROWB);
            float2 vx = __half22float2(*(__half2*)&v.x);
            float2 vy = __half22float2(*(__half2*)&v.y);
            ax.x += vx.x; ax.y += vx.y;
            ay.x += vy.x; ay.y += vy.y;
        }
    }
    if (act) {
        atomicAdd(&g_Msum[cur * DD + 4 * t],     ax.x);
        atomicAdd(&g_Msum[cur * DD + 4 * t + 1], ax.y);
        atomicAdd(&g_Msum[cur * DD + 4 * t + 2], ay.x);
        atomicAdd(&g_Msum[cur * DD + 4 * t + 3], ay.y);
    }
}

// epilogue GEMM step: out[g] = in[g]@W + coef[g]*b          (finalize=0)
//                     out[g] = in[g]@W/max(cnt,1)+(cnt>0)*b (finalize=1)
__global__ void mg_kernel(const float* __restrict__ in, float* __restrict__ outp,
                          const float* __restrict__ W, const float* __restrict__ bvec,
                          const float* __restrict__ coef, int finalize) {
    int g = blockIdx.x;
    int c = threadIdx.x;
    __shared__ float arow[DD];
    for (int k = c; k < DD; k += 320) arow[k] = in[g * DD + k];
    __syncthreads();
    if (c >= DD) return;
    float acc = 0.f;
    #pragma unroll 4
    for (int k = 0; k < DD; ++k) acc += arow[k] * W[k * DD + c];
    if (!finalize) {
        outp[g * DD + c] = acc + coef[g] * bvec[c];
    } else {
        int cnt = g_gcnt[g];
        float denom = (cnt > 0) ? (float)cnt : 1.f;
        float r = acc / denom;
        if (cnt > 0) r += bvec[c];
        outp[g * DD + c] = r;
    }
}

// ---------------- launch ----------------------------------------------------

extern "C" void kernel_launch(void* const* d_in, const int* in_sizes, int n_in,
                              void* d_out, int out_size) {
    const int*   x     = (const int*)d_in[0];     // [N,2]
    const int*   ei    = (const int*)d_in[1];     // [2,E]
    const int*   batch = (const int*)d_in[2];     // [N]
    const float* at    = (const float*)d_in[3];   // [41,300]
    const float* wt    = (const float*)d_in[4];   // [10000,300]
    const float* W     = (const float*)d_in[5];   // [300,300]
    const float* b     = (const float*)d_in[6];   // [300]
    float* out = (float*)d_out;

    __half2 *hA, *hB;
    float *T1, *T2, *Msum, *usum;
    cudaGetSymbolAddress((void**)&hA,   g_hA);
    cudaGetSymbolAddress((void**)&hB,   g_hB);
    cudaGetSymbolAddress((void**)&T1,   g_T1);
    cudaGetSymbolAddress((void**)&T2,   g_T2);
    cudaGetSymbolAddress((void**)&Msum, g_Msum);
    cudaGetSymbolAddress((void**)&usum, g_usum);

    // CSR build (coalesced 3-phase scan; g_cnt self-resetting)
    hist_kernel<<<(NE + 255) / 256, 256>>>(ei);                             // 0
    scan1_kernel<<<NB, 1024>>>();                                           // 1
    scan2_kernel<<<1, 256>>>();                                             // 2
    scan3_kernel<<<NB, 1024>>>();                                           // 3
    scatter_embed_kernel<<<EDGE_BLOCKS + EMB_BLOCKS, 256>>>(ei, x, at, wt); // 4
    // three hops (16B lanes, 2 warps per node)
    agg_step_kernel<<<NN, 64>>>(hA, hB, 0);                                 // 5
    agg_step_kernel<<<NN, 64>>>(hB, hA, 0);                                 // 6
    agg_step_kernel<<<NN, 64>>>(hA, hB, 1);                                 // 7 -> y3 in hB
    // pooling of y3
    pool_kernel<<<(NN + 63) / 64, 96>>>(hB, batch);                         // 8
    // bias-term scalar chain (pass 2 fused with vector pooling)
    aggs1_kernel<<<(NN + 255) / 256, 256>>>();                              // 9
    aggs2_kernel<<<(NN + 255) / 256, 256>>>(batch);                         // 10
    // epilogue: ((Msum@W + u2⊗b)@W + u1⊗b)@W, then /cnt + b
    mg_kernel<<<NG, 320>>>(Msum, T1, W, b, usum + NG, 0);                   // 11
    mg_kernel<<<NG, 320>>>(T1,   T2, W, b, usum,      0);                   // 12
    mg_kernel<<<NG, 320>>>(T2,  out, W, b, usum,      1);                   // 13
}